// round 1
// baseline (speedup 1.0000x reference)
#include <cuda_runtime.h>
#include <cstdint>

// Problem constants
#define Bsz 512
#define Dd  256
#define Kq  65536
#define Cc  1000
#define T_SUPf 0.07f
#define T_DCf  0.1f
#define LSm  0.1f
#define EPSf 1e-8f
#define SPLIT 8

// -------- scratch (static device globals; no allocation allowed) ----------
__device__ float g_sim[(size_t)1024 * Kq];        // rows 0..511: sim(norm_q), 512..1023: simk -> exp weights (in place)
__device__ float g_part[(size_t)SPLIT * 512 * 1024]; // split-K partials for dc GEMM (padded C to 1024)
__device__ float g_invZ[512];
__device__ float g_row_supin[512];
__device__ float g_row_fc[512];
__device__ float g_row_dc[512];
__device__ int   g_is64;

// monotonic float -> uint mapping (order-preserving)
__device__ __forceinline__ unsigned fmap(float f) {
    unsigned u = __float_as_uint(f);
    return (u & 0x80000000u) ? ~u : (u | 0x80000000u);
}

// ---------------------------------------------------------------------------
// int64-vs-int32 probe: queue_label has 65536 entries in [0,1000). If stored
// as int64, every high 32-bit word is 0. If int32, the "high words" are
// actual labels and the chance all 4096 sampled are zero is ~0.
// ---------------------------------------------------------------------------
__global__ void detect_kernel(const int* __restrict__ qlabel_raw) {
    if (threadIdx.x == 0 && blockIdx.x == 0) {
        int is64 = 1;
        for (int i = 0; i < 4096; i++) {
            if (qlabel_raw[2 * i + 1] != 0) { is64 = 0; break; }
        }
        g_is64 = is64;
    }
}

__device__ __forceinline__ long long load_label(const void* p, int i) {
    if (g_is64) return ((const long long*)p)[i];
    return (long long)((const int*)p)[i];
}

// ---------------------------------------------------------------------------
// GEMM1: [norm_q; k_feat] (1024 x 256) @ queue (256 x 65536) -> g_sim
// 64x64 tile, BK=16, 256 threads, 4x4 per-thread register tile.
// ---------------------------------------------------------------------------
__global__ void __launch_bounds__(256) gemm_sims(
    const float* __restrict__ normq,
    const float* __restrict__ kfeat,
    const float* __restrict__ queue)
{
    const int nt = blockIdx.x;   // 0..1023 (column tile)
    const int mt = blockIdx.y;   // 0..15   (row tile)
    const float* A = (mt < 8) ? (normq + (size_t)mt * 64 * Dd)
                              : (kfeat + (size_t)(mt - 8) * 64 * Dd);
    float* out = g_sim + (size_t)mt * 64 * Kq + (size_t)nt * 64;

    __shared__ float As[64][17];
    __shared__ float Bs[16][64];

    const int tid = threadIdx.x;
    const int tx = tid & 15;        // 0..15 -> 4 output cols
    const int ty = tid >> 4;        // 0..15 -> 4 output rows
    const int arow = tid >> 2;          // 0..63
    const int acol = (tid & 3) * 4;     // 0,4,8,12
    const int brow = tid >> 4;          // 0..15
    const int bcol = (tid & 15) * 4;    // 0..60

    float acc[4][4] = {};

    for (int kc = 0; kc < Dd; kc += 16) {
        float4 av = *(const float4*)(A + (size_t)arow * Dd + kc + acol);
        As[arow][acol + 0] = av.x;
        As[arow][acol + 1] = av.y;
        As[arow][acol + 2] = av.z;
        As[arow][acol + 3] = av.w;
        float4 bv = *(const float4*)(queue + (size_t)(kc + brow) * Kq + (size_t)nt * 64 + bcol);
        *(float4*)&Bs[brow][bcol] = bv;
        __syncthreads();
        #pragma unroll
        for (int kk = 0; kk < 16; kk++) {
            float a[4], b[4];
            #pragma unroll
            for (int i = 0; i < 4; i++) a[i] = As[ty * 4 + i][kk];
            #pragma unroll
            for (int j = 0; j < 4; j++) b[j] = Bs[kk][tx * 4 + j];
            #pragma unroll
            for (int i = 0; i < 4; i++)
                #pragma unroll
                for (int j = 0; j < 4; j++)
                    acc[i][j] = fmaf(a[i], b[j], acc[i][j]);
        }
        __syncthreads();
    }

    #pragma unroll
    for (int i = 0; i < 4; i++) {
        float4 v = make_float4(acc[i][0], acc[i][1], acc[i][2], acc[i][3]);
        *(float4*)(out + (size_t)(ty * 4 + i) * Kq + tx * 4) = v;
    }
}

// ---------------------------------------------------------------------------
// supcon: per row of sim, radix-select the 200th largest, then softmax-sum
// over the selected set (ties resolved by lowest index, matching lax.top_k).
// s in [-1,1] so exp(s/T) never overflows -> no max subtraction needed
// (softmax is shift-invariant; gt is a ratio of sums).
// ---------------------------------------------------------------------------
#define MAXTIES 2048
__global__ void __launch_bounds__(256) supcon_kernel(
    const void* __restrict__ qlabel,
    const void* __restrict__ target,
    const int*  __restrict__ knnk)
{
    const int b = blockIdx.x;
    const float* row = g_sim + (size_t)b * Kq;
    const int tid = threadIdx.x;
    const int NT = 256;
    const int kneed = knnk[0];

    __shared__ unsigned hist[256];
    __shared__ unsigned s_prefix, s_desired;
    __shared__ int s_ties;
    __shared__ int tie_idx[MAXTIES];
    __shared__ float ra[256], rp[256];

    if (tid == 0) { s_prefix = 0; s_desired = (unsigned)kneed; }
    __syncthreads();

    for (int pass = 0; pass < 4; pass++) {
        const int shift = 24 - pass * 8;
        for (int i = tid; i < 256; i += NT) hist[i] = 0;
        __syncthreads();
        const unsigned pref = s_prefix;
        for (int k = tid; k < Kq; k += NT) {
            unsigned u = fmap(row[k]);
            bool ok = (pass == 0) || ((u >> (shift + 8)) == pref);
            if (ok) atomicAdd(&hist[(u >> shift) & 255u], 1u);
        }
        __syncthreads();
        if (tid == 0) {
            unsigned des = s_desired;
            for (int bin = 255; bin >= 0; bin--) {
                unsigned c = hist[bin];
                if (c >= des) {
                    s_prefix = (pref << 8) | (unsigned)bin;
                    s_desired = des;
                    break;
                }
                des -= c;
            }
        }
        __syncthreads();
    }

    const unsigned u200 = s_prefix;
    const unsigned des = s_desired;    // number of ties (== u200) to take, lowest index first
    if (tid == 0) s_ties = 0;
    __syncthreads();

    float sa = 0.f, sp = 0.f;
    const long long tgt = load_label(target, b);
    for (int k = tid; k < Kq; k += NT) {
        float sv = row[k];
        unsigned u = fmap(sv);
        if (u > u200) {
            float e = __expf(sv * (1.0f / T_SUPf));
            sa += e;
            if (load_label(qlabel, k) == tgt) sp += e;
        } else if (u == u200) {
            int p = atomicAdd(&s_ties, 1);
            if (p < MAXTIES) tie_idx[p] = k;
        }
    }
    ra[tid] = sa; rp[tid] = sp;
    __syncthreads();
    for (int o = 128; o > 0; o >>= 1) {
        if (tid < o) { ra[tid] += ra[tid + o]; rp[tid] += rp[tid + o]; }
        __syncthreads();
    }

    if (tid == 0) {
        float SA = ra[0], SP = rp[0];
        int t = min(s_ties, MAXTIES);
        // insertion sort ascending by index (t is tiny; usually 1)
        for (int i = 1; i < t; i++) {
            int v = tie_idx[i]; int j = i - 1;
            while (j >= 0 && tie_idx[j] > v) { tie_idx[j + 1] = tie_idx[j]; j--; }
            tie_idx[j + 1] = v;
        }
        int take = min((int)des, t);
        for (int i = 0; i < take; i++) {
            int k = tie_idx[i];
            float e = __expf(row[k] * (1.0f / T_SUPf));
            SA += e;
            if (load_label(qlabel, k) == tgt) SP += e;
        }
        float gt = SP / SA;
        g_row_supin[b] = (gt > EPSf) ? (-__logf(gt)) : 0.0f;
    }
}

// ---------------------------------------------------------------------------
// expz: rows 512..1023 of g_sim (= k_feat @ queue). In place:
//   E = exp(s / T_DC); invZ = 1/sum(E).  (|s|<=1 -> no overflow.)
// ---------------------------------------------------------------------------
__global__ void __launch_bounds__(256) expz_kernel() {
    const int b = blockIdx.x;
    float* row = g_sim + (size_t)(512 + b) * Kq;
    const int tid = threadIdx.x;
    float s = 0.f;
    float4* row4 = (float4*)row;
    for (int k = tid; k < Kq / 4; k += 256) {
        float4 v = row4[k];
        v.x = __expf(v.x * (1.0f / T_DCf));
        v.y = __expf(v.y * (1.0f / T_DCf));
        v.z = __expf(v.z * (1.0f / T_DCf));
        v.w = __expf(v.w * (1.0f / T_DCf));
        row4[k] = v;
        s += v.x + v.y + v.z + v.w;
    }
    __shared__ float red[256];
    red[tid] = s;
    __syncthreads();
    for (int o = 128; o > 0; o >>= 1) {
        if (tid < o) red[tid] += red[tid + o];
        __syncthreads();
    }
    if (tid == 0) g_invZ[b] = 1.0f / red[0];
}

// ---------------------------------------------------------------------------
// GEMM2 (split-K): part[sp] += E(512 x 65536) @ P^T(65536 x 1000)
// Both operands are K-contiguous ("NT" form). 64x64 tile, BK=16, split-K=8.
// ---------------------------------------------------------------------------
__global__ void __launch_bounds__(256) gemm_dc(const float* __restrict__ P)
{
    const int nt = blockIdx.x;   // 0..15 (c tile; padded to 1024)
    const int mt = blockIdx.y;   // 0..7
    const int sp = blockIdx.z;   // 0..SPLIT-1
    const float* E = g_sim + (size_t)512 * Kq + (size_t)mt * 64 * Kq;

    __shared__ float As[64][17];
    __shared__ float Bs[64][17];

    const int tid = threadIdx.x;
    const int tx = tid & 15, ty = tid >> 4;
    const int lrow = tid >> 2;          // 0..63
    const int lcol = (tid & 3) * 4;     // 0,4,8,12
    const int c_load = nt * 64 + lrow;

    float acc[4][4] = {};
    const int k0 = sp * (Kq / SPLIT);

    for (int kc = 0; kc < Kq / SPLIT; kc += 16) {
        float4 av = *(const float4*)(E + (size_t)lrow * Kq + k0 + kc + lcol);
        As[lrow][lcol + 0] = av.x;
        As[lrow][lcol + 1] = av.y;
        As[lrow][lcol + 2] = av.z;
        As[lrow][lcol + 3] = av.w;
        float4 bv = make_float4(0.f, 0.f, 0.f, 0.f);
        if (c_load < Cc)
            bv = *(const float4*)(P + (size_t)c_load * Kq + k0 + kc + lcol);
        Bs[lrow][lcol + 0] = bv.x;
        Bs[lrow][lcol + 1] = bv.y;
        Bs[lrow][lcol + 2] = bv.z;
        Bs[lrow][lcol + 3] = bv.w;
        __syncthreads();
        #pragma unroll
        for (int kk = 0; kk < 16; kk++) {
            float a[4], b[4];
            #pragma unroll
            for (int i = 0; i < 4; i++) a[i] = As[ty * 4 + i][kk];
            #pragma unroll
            for (int j = 0; j < 4; j++) b[j] = Bs[tx * 4 + j][kk];
            #pragma unroll
            for (int i = 0; i < 4; i++)
                #pragma unroll
                for (int j = 0; j < 4; j++)
                    acc[i][j] = fmaf(a[i], b[j], acc[i][j]);
        }
        __syncthreads();
    }

    float* pp = g_part + ((size_t)sp * 512 + (size_t)mt * 64) * 1024 + (size_t)nt * 64;
    #pragma unroll
    for (int i = 0; i < 4; i++) {
        float4 v = make_float4(acc[i][0], acc[i][1], acc[i][2], acc[i][3]);
        *(float4*)(pp + (size_t)(ty * 4 + i) * 1024 + tx * 4) = v;
    }
}

// ---------------------------------------------------------------------------
// fc + dc per-row losses (C=1000 loops), folding the split-K reduce + invZ.
// ---------------------------------------------------------------------------
__global__ void __launch_bounds__(256) fcdc_kernel(
    const float* __restrict__ qlog,
    const void* __restrict__ target)
{
    const int b = blockIdx.x;
    const int tid = threadIdx.x;
    const float* q = qlog + (size_t)b * Cc;
    __shared__ float red[256];

    // max
    float mx = -3.4e38f;
    for (int c = tid; c < Cc; c += 256) mx = fmaxf(mx, q[c]);
    red[tid] = mx; __syncthreads();
    for (int o = 128; o > 0; o >>= 1) { if (tid < o) red[tid] = fmaxf(red[tid], red[tid + o]); __syncthreads(); }
    const float Mx = red[0]; __syncthreads();

    // min
    float mn = 3.4e38f;
    for (int c = tid; c < Cc; c += 256) mn = fminf(mn, q[c]);
    red[tid] = mn; __syncthreads();
    for (int o = 128; o > 0; o >>= 1) { if (tid < o) red[tid] = fminf(red[tid], red[tid + o]); __syncthreads(); }
    const float Mn = red[0]; __syncthreads();

    // sum exp
    float se = 0.f;
    for (int c = tid; c < Cc; c += 256) se += __expf(q[c] - Mx);
    red[tid] = se; __syncthreads();
    for (int o = 128; o > 0; o >>= 1) { if (tid < o) red[tid] += red[tid + o]; __syncthreads(); }
    const float SE = red[0]; __syncthreads();

    const float logZ = __logf(SE);
    const bool qmask = (__expf(Mn - Mx) / SE) > EPSf;
    const float invZk = g_invZ[b];
    const long long t = load_label(target, b);

    float fcs = 0.f, kl = 0.f;
    for (int c = tid; c < Cc; c += 256) {
        float lq = q[c] - Mx - logZ;
        float oh = (c == (int)t) ? (1.0f - LSm) : (LSm / (float)(Cc - 1));
        fcs += oh * lq;
        float ps = 0.f;
        #pragma unroll
        for (int s = 0; s < SPLIT; s++)
            ps += g_part[((size_t)s * 512 + b) * 1024 + c];
        float dct = invZk * ps;
        if (dct > 0.f) kl += dct * (__logf(dct) - lq);
    }
    red[tid] = fcs; __syncthreads();
    for (int o = 128; o > 0; o >>= 1) { if (tid < o) red[tid] += red[tid + o]; __syncthreads(); }
    const float FCS = red[0]; __syncthreads();
    red[tid] = kl; __syncthreads();
    for (int o = 128; o > 0; o >>= 1) { if (tid < o) red[tid] += red[tid + o]; __syncthreads(); }
    if (tid == 0) {
        g_row_fc[b] = qmask ? FCS : 0.f;
        g_row_dc[b] = qmask ? red[0] : 0.f;
    }
}

// ---------------------------------------------------------------------------
// finalize: reduce 512 per-row values -> 3 output scalars.
// ---------------------------------------------------------------------------
__global__ void __launch_bounds__(512) finalize_kernel(float* __restrict__ out) {
    const int tid = threadIdx.x;
    __shared__ float r[512];

    r[tid] = g_row_supin[tid]; __syncthreads();
    for (int o = 256; o > 0; o >>= 1) { if (tid < o) r[tid] += r[tid + o]; __syncthreads(); }
    if (tid == 0) out[0] = r[0] / (float)Bsz;
    __syncthreads();

    r[tid] = g_row_fc[tid]; __syncthreads();
    for (int o = 256; o > 0; o >>= 1) { if (tid < o) r[tid] += r[tid + o]; __syncthreads(); }
    if (tid == 0) out[1] = -r[0] / (float)Bsz;
    __syncthreads();

    r[tid] = g_row_dc[tid]; __syncthreads();
    for (int o = 256; o > 0; o >>= 1) { if (tid < o) r[tid] += r[tid + o]; __syncthreads(); }
    if (tid == 0) out[2] = r[0] / (float)Bsz;
}

// ---------------------------------------------------------------------------
extern "C" void kernel_launch(void* const* d_in, const int* in_sizes, int n_in,
                              void* d_out, int out_size)
{
    const float* normq  = (const float*)d_in[0];
    const float* qlog   = (const float*)d_in[1];
    const float* kfeat  = (const float*)d_in[2];
    // d_in[3] = logits_k (unused by the reference)
    const float* queue  = (const float*)d_in[4];
    const float* qlp    = (const float*)d_in[5];
    const void*  qlabel = d_in[6];
    const void*  target = d_in[7];
    const int*   knnk   = (const int*)d_in[8];  // low 32 bits valid for int32 or int64
    float* out = (float*)d_out;

    detect_kernel<<<1, 32>>>((const int*)qlabel);
    gemm_sims<<<dim3(Kq / 64, 16), 256>>>(normq, kfeat, queue);
    supcon_kernel<<<512, 256>>>(qlabel, target, knnk);
    expz_kernel<<<512, 256>>>();
    gemm_dc<<<dim3(16, 8, SPLIT), 256>>>(qlp);
    fcdc_kernel<<<512, 256>>>(qlog, target);
    finalize_kernel<<<1, 512>>>(out);
    (void)in_sizes; (void)n_in; (void)out_size;
}

// round 2
// speedup vs baseline: 1.7185x; 1.7185x over previous
#include <cuda_runtime.h>
#include <cuda_bf16.h>
#include <cstdint>

// Problem constants
#define Bsz 512
#define Dd  256
#define Kq  65536
#define Cc  1000
#define T_SUPf 0.07f
#define T_DCf  0.1f
#define LSm  0.1f
#define EPSf 1e-8f
#define SPLIT 8

// -------- scratch (static device globals; no allocation allowed) ----------
__device__ float g_sim[(size_t)512 * Kq];            // sim(norm_q) rows only (fp32, for radix top-k)
__device__ __nv_bfloat16 g_Ehi[(size_t)512 * Kq];    // exp(sim_k/T_DC) split hi
__device__ __nv_bfloat16 g_Elo[(size_t)512 * Kq];    // exp(sim_k/T_DC) split lo
__device__ float g_psum[(size_t)512 * 2048];         // per-(ntile,warp-n) row-sum partials of E
__device__ float g_part[(size_t)SPLIT * 512 * 1024]; // split-K partials for dc GEMM (C padded to 1024)
__device__ float g_invZ[512];
__device__ float g_row_supin[512];
__device__ float g_row_fc[512];
__device__ float g_row_dc[512];
__device__ int   g_is64;

// monotonic float -> uint mapping (order-preserving)
__device__ __forceinline__ unsigned fmap(float f) {
    unsigned u = __float_as_uint(f);
    return (u & 0x80000000u) ? ~u : (u | 0x80000000u);
}

// ---------------------------------------------------------------------------
// int64-vs-int32 probe for the label arrays.
// ---------------------------------------------------------------------------
__global__ void detect_kernel(const int* __restrict__ qlabel_raw) {
    if (threadIdx.x == 0 && blockIdx.x == 0) {
        int is64 = 1;
        for (int i = 0; i < 4096; i++) {
            if (qlabel_raw[2 * i + 1] != 0) { is64 = 0; break; }
        }
        g_is64 = is64;
    }
}

__device__ __forceinline__ long long load_label(const void* p, int i) {
    if (g_is64) return ((const long long*)p)[i];
    return (long long)((const int*)p)[i];
}

// ---------------------------------------------------------------------------
// mma.sync m16n8k16 bf16 wrapper + split helpers
// ---------------------------------------------------------------------------
__device__ __forceinline__ void mma_bf16(float* c, uint32_t a0, uint32_t a1,
                                         uint32_t a2, uint32_t a3,
                                         uint32_t b0, uint32_t b1) {
    asm volatile(
        "mma.sync.aligned.m16n8k16.row.col.f32.bf16.bf16.f32 "
        "{%0,%1,%2,%3}, {%4,%5,%6,%7}, {%8,%9}, {%0,%1,%2,%3};\n"
        : "+f"(c[0]), "+f"(c[1]), "+f"(c[2]), "+f"(c[3])
        : "r"(a0), "r"(a1), "r"(a2), "r"(a3), "r"(b0), "r"(b1));
}

// split two fp32 into packed bf16 hi/lo words (elem0 in low half)
__device__ __forceinline__ void split2(float f0, float f1, uint32_t& hi, uint32_t& lo) {
    __nv_bfloat16 h0 = __float2bfloat16(f0), h1 = __float2bfloat16(f1);
    float r0 = f0 - __bfloat162float(h0);
    float r1 = f1 - __bfloat162float(h1);
    __nv_bfloat16 l0 = __float2bfloat16(r0), l1 = __float2bfloat16(r1);
    hi = ((uint32_t)__bfloat16_as_ushort(h1) << 16) | (uint32_t)__bfloat16_as_ushort(h0);
    lo = ((uint32_t)__bfloat16_as_ushort(l1) << 16) | (uint32_t)__bfloat16_as_ushort(l0);
}

// ---------------------------------------------------------------------------
// GEMM1 (tensor): [norm_q; k_feat](1024x256) @ queue(256x65536)
// CTA tile 128x128, kc=32, 8 warps as 2(M)x4(N); warp tile 64x32.
// Rows <512 -> fp32 sim; rows >=512 -> fused exp -> bf16 hi/lo E + row-sum partials.
// ---------------------------------------------------------------------------
__global__ void __launch_bounds__(256) gemm1_kernel(
    const float* __restrict__ normq,
    const float* __restrict__ kfeat,
    const float* __restrict__ queue)
{
    const int nt = blockIdx.x;   // 0..511
    const int mt = blockIdx.y;   // 0..7

    __shared__ __align__(16) uint32_t As_hi[128][20];
    __shared__ __align__(16) uint32_t As_lo[128][20];
    __shared__ __align__(16) uint32_t Bs_hi[128][20];
    __shared__ __align__(16) uint32_t Bs_lo[128][20];

    const int tid = threadIdx.x;
    const int lane = tid & 31, wid = tid >> 5;
    const int wm = wid >> 2, wn = wid & 3;       // 2 x 4
    const int g = lane >> 2, tig = lane & 3;

    const float* A = (mt < 4) ? (normq + (size_t)mt * 128 * Dd)
                              : (kfeat + (size_t)(mt - 4) * 128 * Dd);

    float acc[4][4][4] = {};

    const int a_row = tid >> 1;               // 0..127
    const int a_k = (tid & 1) * 16;           // 0 or 16
    const int b_d = tid >> 3;                 // 0..31
    const int b_n0 = (tid & 7) * 16;          // 0..112

    for (int kc = 0; kc < Dd; kc += 32) {
        // ---- load A (fp32 -> split bf16 packed) ----
        #pragma unroll
        for (int i = 0; i < 4; i++) {
            float4 v = *(const float4*)(A + (size_t)a_row * Dd + kc + a_k + i * 4);
            uint32_t h0, l0, h1, l1;
            split2(v.x, v.y, h0, l0);
            split2(v.z, v.w, h1, l1);
            int w = (a_k + i * 4) >> 1;
            As_hi[a_row][w]     = h0; As_hi[a_row][w + 1] = h1;
            As_lo[a_row][w]     = l0; As_lo[a_row][w + 1] = l1;
        }
        // ---- load B (queue, [d][n] fp32 -> smem [n][d/2] packed) ----
        #pragma unroll
        for (int i = 0; i < 4; i++) {
            float4 v = *(const float4*)(queue + (size_t)(kc + b_d) * Kq + (size_t)nt * 128 + b_n0 + i * 4);
            int w = b_d >> 1, half = b_d & 1;
            float fs[4] = {v.x, v.y, v.z, v.w};
            #pragma unroll
            for (int j = 0; j < 4; j++) {
                int n = b_n0 + i * 4 + j;
                __nv_bfloat16 h = __float2bfloat16(fs[j]);
                float r = fs[j] - __bfloat162float(h);
                __nv_bfloat16 l = __float2bfloat16(r);
                ((__nv_bfloat16*)&Bs_hi[n][w])[half] = h;
                ((__nv_bfloat16*)&Bs_lo[n][w])[half] = l;
            }
        }
        __syncthreads();

        #pragma unroll
        for (int ks = 0; ks < 2; ks++) {
            const int w = ks * 8 + tig;
            uint32_t ah[4][4], al[4][4];
            #pragma unroll
            for (int m = 0; m < 4; m++) {
                int r0 = wm * 64 + m * 16 + g, r1 = r0 + 8;
                ah[m][0] = As_hi[r0][w];     ah[m][1] = As_hi[r1][w];
                ah[m][2] = As_hi[r0][w + 4]; ah[m][3] = As_hi[r1][w + 4];
                al[m][0] = As_lo[r0][w];     al[m][1] = As_lo[r1][w];
                al[m][2] = As_lo[r0][w + 4]; al[m][3] = As_lo[r1][w + 4];
            }
            #pragma unroll
            for (int n = 0; n < 4; n++) {
                int nr = wn * 32 + n * 8 + g;
                uint32_t bh0 = Bs_hi[nr][w], bh1 = Bs_hi[nr][w + 4];
                uint32_t bl0 = Bs_lo[nr][w], bl1 = Bs_lo[nr][w + 4];
                #pragma unroll
                for (int m = 0; m < 4; m++) {
                    mma_bf16(acc[m][n], ah[m][0], ah[m][1], ah[m][2], ah[m][3], bh0, bh1);
                    mma_bf16(acc[m][n], ah[m][0], ah[m][1], ah[m][2], ah[m][3], bl0, bl1);
                    mma_bf16(acc[m][n], al[m][0], al[m][1], al[m][2], al[m][3], bh0, bh1);
                }
            }
        }
        __syncthreads();
    }

    // ---- epilogue ----
    const int rbase = mt * 128 + wm * 64;
    const int col = nt * 128 + wn * 32;
    if (mt < 4) {
        #pragma unroll
        for (int m = 0; m < 4; m++) {
            int r0 = rbase + m * 16 + g;
            #pragma unroll
            for (int n = 0; n < 4; n++) {
                int c = col + n * 8 + tig * 2;
                *(float2*)&g_sim[(size_t)r0 * Kq + c] = make_float2(acc[m][n][0], acc[m][n][1]);
                *(float2*)&g_sim[(size_t)(r0 + 8) * Kq + c] = make_float2(acc[m][n][2], acc[m][n][3]);
            }
        }
    } else {
        #pragma unroll
        for (int m = 0; m < 4; m++) {
            int b0 = rbase - 512 + m * 16 + g;
            float s0 = 0.f, s1 = 0.f;
            #pragma unroll
            for (int n = 0; n < 4; n++) {
                int c = col + n * 8 + tig * 2;
                float e0 = __expf(acc[m][n][0] * (1.0f / T_DCf));
                float e1 = __expf(acc[m][n][1] * (1.0f / T_DCf));
                float e2 = __expf(acc[m][n][2] * (1.0f / T_DCf));
                float e3 = __expf(acc[m][n][3] * (1.0f / T_DCf));
                uint32_t h, l;
                split2(e0, e1, h, l);
                *(uint32_t*)&g_Ehi[(size_t)b0 * Kq + c] = h;
                *(uint32_t*)&g_Elo[(size_t)b0 * Kq + c] = l;
                split2(e2, e3, h, l);
                *(uint32_t*)&g_Ehi[(size_t)(b0 + 8) * Kq + c] = h;
                *(uint32_t*)&g_Elo[(size_t)(b0 + 8) * Kq + c] = l;
                s0 += e0 + e1;
                s1 += e2 + e3;
            }
            s0 += __shfl_xor_sync(0xffffffffu, s0, 1);
            s0 += __shfl_xor_sync(0xffffffffu, s0, 2);
            s1 += __shfl_xor_sync(0xffffffffu, s1, 1);
            s1 += __shfl_xor_sync(0xffffffffu, s1, 2);
            if (tig == 0) {
                g_psum[(size_t)b0 * 2048 + nt * 4 + wn] = s0;
                g_psum[(size_t)(b0 + 8) * 2048 + nt * 4 + wn] = s1;
            }
        }
    }
}

// ---------------------------------------------------------------------------
// invz: deterministic reduce of the 2048 per-tile partials -> 1/Z per row.
// ---------------------------------------------------------------------------
__global__ void __launch_bounds__(256) invz_kernel() {
    const int b = blockIdx.x;
    const int tid = threadIdx.x;
    float s = 0.f;
    for (int i = tid; i < 2048; i += 256) s += g_psum[(size_t)b * 2048 + i];
    __shared__ float red[256];
    red[tid] = s;
    __syncthreads();
    for (int o = 128; o > 0; o >>= 1) {
        if (tid < o) red[tid] += red[tid + o];
        __syncthreads();
    }
    if (tid == 0) g_invZ[b] = 1.0f / red[0];
}

// ---------------------------------------------------------------------------
// supcon: radix-select 200th largest per row + softmax-set sums (unchanged).
// ---------------------------------------------------------------------------
#define MAXTIES 2048
__global__ void __launch_bounds__(256) supcon_kernel(
    const void* __restrict__ qlabel,
    const void* __restrict__ target,
    const int*  __restrict__ knnk)
{
    const int b = blockIdx.x;
    const float* row = g_sim + (size_t)b * Kq;
    const int tid = threadIdx.x;
    const int NT = 256;
    const int kneed = knnk[0];

    __shared__ unsigned hist[256];
    __shared__ unsigned s_prefix, s_desired;
    __shared__ int s_ties;
    __shared__ int tie_idx[MAXTIES];
    __shared__ float ra[256], rp[256];

    if (tid == 0) { s_prefix = 0; s_desired = (unsigned)kneed; }
    __syncthreads();

    for (int pass = 0; pass < 4; pass++) {
        const int shift = 24 - pass * 8;
        for (int i = tid; i < 256; i += NT) hist[i] = 0;
        __syncthreads();
        const unsigned pref = s_prefix;
        for (int k = tid; k < Kq; k += NT) {
            unsigned u = fmap(row[k]);
            bool ok = (pass == 0) || ((u >> (shift + 8)) == pref);
            if (ok) atomicAdd(&hist[(u >> shift) & 255u], 1u);
        }
        __syncthreads();
        if (tid == 0) {
            unsigned des = s_desired;
            for (int bin = 255; bin >= 0; bin--) {
                unsigned c = hist[bin];
                if (c >= des) {
                    s_prefix = (pref << 8) | (unsigned)bin;
                    s_desired = des;
                    break;
                }
                des -= c;
            }
        }
        __syncthreads();
    }

    const unsigned u200 = s_prefix;
    const unsigned des = s_desired;
    if (tid == 0) s_ties = 0;
    __syncthreads();

    float sa = 0.f, sp = 0.f;
    const long long tgt = load_label(target, b);
    for (int k = tid; k < Kq; k += NT) {
        float sv = row[k];
        unsigned u = fmap(sv);
        if (u > u200) {
            float e = __expf(sv * (1.0f / T_SUPf));
            sa += e;
            if (load_label(qlabel, k) == tgt) sp += e;
        } else if (u == u200) {
            int p = atomicAdd(&s_ties, 1);
            if (p < MAXTIES) tie_idx[p] = k;
        }
    }
    ra[tid] = sa; rp[tid] = sp;
    __syncthreads();
    for (int o = 128; o > 0; o >>= 1) {
        if (tid < o) { ra[tid] += ra[tid + o]; rp[tid] += rp[tid + o]; }
        __syncthreads();
    }

    if (tid == 0) {
        float SA = ra[0], SP = rp[0];
        int t = min(s_ties, MAXTIES);
        for (int i = 1; i < t; i++) {
            int v = tie_idx[i]; int j = i - 1;
            while (j >= 0 && tie_idx[j] > v) { tie_idx[j + 1] = tie_idx[j]; j--; }
            tie_idx[j + 1] = v;
        }
        int take = min((int)des, t);
        for (int i = 0; i < take; i++) {
            int k = tie_idx[i];
            float e = __expf(row[k] * (1.0f / T_SUPf));
            SA += e;
            if (load_label(qlabel, k) == tgt) SP += e;
        }
        float gt = SP / SA;
        g_row_supin[b] = (gt > EPSf) ? (-__logf(gt)) : 0.0f;
    }
}

// ---------------------------------------------------------------------------
// GEMM2 (tensor, split-K): part[sp] = E(512x65536 bf16 hi/lo) @ P^T(65536x1000)
// CTA tile 128x64, kc=32, 8 warps as 4(M)x2(N); warp tile 32x32.
// ---------------------------------------------------------------------------
__global__ void __launch_bounds__(256) gemm2_kernel(const float* __restrict__ P)
{
    const int nt = blockIdx.x;   // 0..15
    const int mt = blockIdx.y;   // 0..3
    const int sp = blockIdx.z;   // 0..7

    __shared__ __align__(16) uint32_t As_hi[128][20];
    __shared__ __align__(16) uint32_t As_lo[128][20];
    __shared__ __align__(16) uint32_t Bs_hi[64][20];
    __shared__ __align__(16) uint32_t Bs_lo[64][20];

    const int tid = threadIdx.x;
    const int lane = tid & 31, wid = tid >> 5;
    const int wm = wid >> 1, wn = wid & 1;       // 4 x 2
    const int g = lane >> 2, tig = lane & 3;

    float acc[2][4][4] = {};

    const int a_m = tid >> 1;                 // 0..127
    const int a_k = (tid & 1) * 16;           // 0 or 16
    const int b_c = tid >> 2;                 // 0..63
    const int b_k = (tid & 3) * 8;            // 0..24
    const int c_glob = nt * 64 + b_c;
    const bool c_ok = (c_glob < Cc);

    const size_t k0 = (size_t)sp * (Kq / SPLIT);
    const __nv_bfloat16* Ah = g_Ehi + (size_t)(mt * 128) * Kq;
    const __nv_bfloat16* Al = g_Elo + (size_t)(mt * 128) * Kq;
    const float* Pr = c_ok ? (P + (size_t)c_glob * Kq + k0) : nullptr;

    for (int kc = 0; kc < Kq / SPLIT; kc += 32) {
        // ---- A: bf16 already split; 2x uint4 each array ----
        {
            const size_t off = (size_t)a_m * Kq + k0 + kc + a_k;
            uint4 v0 = *(const uint4*)(Ah + off);
            uint4 v1 = *(const uint4*)(Ah + off + 8);
            *(uint4*)&As_hi[a_m][a_k >> 1] = v0;
            *(uint4*)&As_hi[a_m][(a_k >> 1) + 4] = v1;
            uint4 w0 = *(const uint4*)(Al + off);
            uint4 w1 = *(const uint4*)(Al + off + 8);
            *(uint4*)&As_lo[a_m][a_k >> 1] = w0;
            *(uint4*)&As_lo[a_m][(a_k >> 1) + 4] = w1;
        }
        // ---- B: P fp32 -> split bf16 packed ----
        {
            float4 u0 = make_float4(0.f, 0.f, 0.f, 0.f);
            float4 u1 = make_float4(0.f, 0.f, 0.f, 0.f);
            if (c_ok) {
                u0 = *(const float4*)(Pr + kc + b_k);
                u1 = *(const float4*)(Pr + kc + b_k + 4);
            }
            uint32_t h, l;
            int w = b_k >> 1;
            split2(u0.x, u0.y, h, l); Bs_hi[b_c][w] = h;     Bs_lo[b_c][w] = l;
            split2(u0.z, u0.w, h, l); Bs_hi[b_c][w + 1] = h; Bs_lo[b_c][w + 1] = l;
            split2(u1.x, u1.y, h, l); Bs_hi[b_c][w + 2] = h; Bs_lo[b_c][w + 2] = l;
            split2(u1.z, u1.w, h, l); Bs_hi[b_c][w + 3] = h; Bs_lo[b_c][w + 3] = l;
        }
        __syncthreads();

        #pragma unroll
        for (int ks = 0; ks < 2; ks++) {
            const int w = ks * 8 + tig;
            uint32_t ah[2][4], al[2][4];
            #pragma unroll
            for (int m = 0; m < 2; m++) {
                int r0 = wm * 32 + m * 16 + g, r1 = r0 + 8;
                ah[m][0] = As_hi[r0][w];     ah[m][1] = As_hi[r1][w];
                ah[m][2] = As_hi[r0][w + 4]; ah[m][3] = As_hi[r1][w + 4];
                al[m][0] = As_lo[r0][w];     al[m][1] = As_lo[r1][w];
                al[m][2] = As_lo[r0][w + 4]; al[m][3] = As_lo[r1][w + 4];
            }
            #pragma unroll
            for (int n = 0; n < 4; n++) {
                int nr = wn * 32 + n * 8 + g;
                uint32_t bh0 = Bs_hi[nr][w], bh1 = Bs_hi[nr][w + 4];
                uint32_t bl0 = Bs_lo[nr][w], bl1 = Bs_lo[nr][w + 4];
                #pragma unroll
                for (int m = 0; m < 2; m++) {
                    mma_bf16(acc[m][n], ah[m][0], ah[m][1], ah[m][2], ah[m][3], bh0, bh1);
                    mma_bf16(acc[m][n], ah[m][0], ah[m][1], ah[m][2], ah[m][3], bl0, bl1);
                    mma_bf16(acc[m][n], al[m][0], al[m][1], al[m][2], al[m][3], bh0, bh1);
                }
            }
        }
        __syncthreads();
    }

    // ---- epilogue: split-K partials ----
    #pragma unroll
    for (int m = 0; m < 2; m++) {
        int b = mt * 128 + wm * 32 + m * 16 + g;
        #pragma unroll
        for (int n = 0; n < 4; n++) {
            int c = nt * 64 + wn * 32 + n * 8 + tig * 2;
            *(float2*)&g_part[((size_t)sp * 512 + b) * 1024 + c] =
                make_float2(acc[m][n][0], acc[m][n][1]);
            *(float2*)&g_part[((size_t)sp * 512 + b + 8) * 1024 + c] =
                make_float2(acc[m][n][2], acc[m][n][3]);
        }
    }
}

// ---------------------------------------------------------------------------
// fc + dc per-row losses (unchanged).
// ---------------------------------------------------------------------------
__global__ void __launch_bounds__(256) fcdc_kernel(
    const float* __restrict__ qlog,
    const void* __restrict__ target)
{
    const int b = blockIdx.x;
    const int tid = threadIdx.x;
    const float* q = qlog + (size_t)b * Cc;
    __shared__ float red[256];

    float mx = -3.4e38f;
    for (int c = tid; c < Cc; c += 256) mx = fmaxf(mx, q[c]);
    red[tid] = mx; __syncthreads();
    for (int o = 128; o > 0; o >>= 1) { if (tid < o) red[tid] = fmaxf(red[tid], red[tid + o]); __syncthreads(); }
    const float Mx = red[0]; __syncthreads();

    float mn = 3.4e38f;
    for (int c = tid; c < Cc; c += 256) mn = fminf(mn, q[c]);
    red[tid] = mn; __syncthreads();
    for (int o = 128; o > 0; o >>= 1) { if (tid < o) red[tid] = fminf(red[tid], red[tid + o]); __syncthreads(); }
    const float Mn = red[0]; __syncthreads();

    float se = 0.f;
    for (int c = tid; c < Cc; c += 256) se += __expf(q[c] - Mx);
    red[tid] = se; __syncthreads();
    for (int o = 128; o > 0; o >>= 1) { if (tid < o) red[tid] += red[tid + o]; __syncthreads(); }
    const float SE = red[0]; __syncthreads();

    const float logZ = __logf(SE);
    const bool qmask = (__expf(Mn - Mx) / SE) > EPSf;
    const float invZk = g_invZ[b];
    const long long t = load_label(target, b);

    float fcs = 0.f, kl = 0.f;
    for (int c = tid; c < Cc; c += 256) {
        float lq = q[c] - Mx - logZ;
        float oh = (c == (int)t) ? (1.0f - LSm) : (LSm / (float)(Cc - 1));
        fcs += oh * lq;
        float ps = 0.f;
        #pragma unroll
        for (int s = 0; s < SPLIT; s++)
            ps += g_part[((size_t)s * 512 + b) * 1024 + c];
        float dct = invZk * ps;
        if (dct > 0.f) kl += dct * (__logf(dct) - lq);
    }
    red[tid] = fcs; __syncthreads();
    for (int o = 128; o > 0; o >>= 1) { if (tid < o) red[tid] += red[tid + o]; __syncthreads(); }
    const float FCS = red[0]; __syncthreads();
    red[tid] = kl; __syncthreads();
    for (int o = 128; o > 0; o >>= 1) { if (tid < o) red[tid] += red[tid + o]; __syncthreads(); }
    if (tid == 0) {
        g_row_fc[b] = qmask ? FCS : 0.f;
        g_row_dc[b] = qmask ? red[0] : 0.f;
    }
}

// ---------------------------------------------------------------------------
// finalize: reduce 512 per-row values -> 3 output scalars.
// ---------------------------------------------------------------------------
__global__ void __launch_bounds__(512) finalize_kernel(float* __restrict__ out) {
    const int tid = threadIdx.x;
    __shared__ float r[512];

    r[tid] = g_row_supin[tid]; __syncthreads();
    for (int o = 256; o > 0; o >>= 1) { if (tid < o) r[tid] += r[tid + o]; __syncthreads(); }
    if (tid == 0) out[0] = r[0] / (float)Bsz;
    __syncthreads();

    r[tid] = g_row_fc[tid]; __syncthreads();
    for (int o = 256; o > 0; o >>= 1) { if (tid < o) r[tid] += r[tid + o]; __syncthreads(); }
    if (tid == 0) out[1] = -r[0] / (float)Bsz;
    __syncthreads();

    r[tid] = g_row_dc[tid]; __syncthreads();
    for (int o = 256; o > 0; o >>= 1) { if (tid < o) r[tid] += r[tid + o]; __syncthreads(); }
    if (tid == 0) out[2] = r[0] / (float)Bsz;
}

// ---------------------------------------------------------------------------
extern "C" void kernel_launch(void* const* d_in, const int* in_sizes, int n_in,
                              void* d_out, int out_size)
{
    const float* normq  = (const float*)d_in[0];
    const float* qlog   = (const float*)d_in[1];
    const float* kfeat  = (const float*)d_in[2];
    // d_in[3] = logits_k (unused by the reference)
    const float* queue  = (const float*)d_in[4];
    const float* qlp    = (const float*)d_in[5];
    const void*  qlabel = d_in[6];
    const void*  target = d_in[7];
    const int*   knnk   = (const int*)d_in[8];
    float* out = (float*)d_out;

    detect_kernel<<<1, 32>>>((const int*)qlabel);
    gemm1_kernel<<<dim3(Kq / 128, 8), 256>>>(normq, kfeat, queue);
    supcon_kernel<<<512, 256>>>(qlabel, target, knnk);
    invz_kernel<<<512, 256>>>();
    gemm2_kernel<<<dim3(16, 4, SPLIT), 256>>>(qlp);
    fcdc_kernel<<<512, 256>>>(qlog, target);
    finalize_kernel<<<1, 512>>>(out);
    (void)in_sizes; (void)n_in; (void)out_size;
}

// round 4
// speedup vs baseline: 2.2237x; 1.2940x over previous
#include <cuda_runtime.h>
#include <cuda_bf16.h>
#include <cstdint>

// Problem constants
#define Bsz 512
#define Dd  256
#define Kq  65536
#define Cc  1000
#define Cpad 1024
#define T_SUPf 0.07f
#define T_DCf  0.1f
#define LSm  0.1f
#define EPSf 1e-8f
#define SPLIT 8
#define PADW 20   // 16 data words + 4 pad per row

// -------- scratch (static device globals) ----------
__device__ float g_sim[(size_t)512 * Kq];
__device__ __align__(16) __nv_bfloat16 g_Ehi[(size_t)512 * Kq];
__device__ __align__(16) __nv_bfloat16 g_Elo[(size_t)512 * Kq];
__device__ __align__(16) __nv_bfloat16 g_Ahi[(size_t)1024 * Dd];
__device__ __align__(16) __nv_bfloat16 g_Alo[(size_t)1024 * Dd];
__device__ __align__(16) __nv_bfloat16 g_QThi[(size_t)Kq * Dd];
__device__ __align__(16) __nv_bfloat16 g_QTlo[(size_t)Kq * Dd];
__device__ __align__(16) __nv_bfloat16 g_Phi[(size_t)Cpad * Kq];
__device__ __align__(16) __nv_bfloat16 g_Plo[(size_t)Cpad * Kq];
__device__ float g_psum[(size_t)512 * 2048];
__device__ float g_part[(size_t)SPLIT * 512 * Cpad];
__device__ float g_invZ[512];
__device__ float g_row_supin[512];
__device__ float g_row_fc[512];
__device__ float g_row_dc[512];
__device__ int   g_is64;

// ---------------- helpers ----------------
__device__ __forceinline__ uint32_t smem_u32(const void* p) {
    uint32_t a;
    asm("{ .reg .u64 t; cvta.to.shared.u64 t, %1; cvt.u32.u64 %0, t; }" : "=r"(a) : "l"(p));
    return a;
}
__device__ __forceinline__ void cp16(uint32_t dst, const void* src) {
    asm volatile("cp.async.cg.shared.global [%0], [%1], 16;\n" :: "r"(dst), "l"(src));
}
#define CPCOMMIT() asm volatile("cp.async.commit_group;\n" ::: "memory")

__device__ __forceinline__ void mma_bf16(float* c, uint32_t a0, uint32_t a1,
                                         uint32_t a2, uint32_t a3,
                                         uint32_t b0, uint32_t b1) {
    asm volatile(
        "mma.sync.aligned.m16n8k16.row.col.f32.bf16.bf16.f32 "
        "{%0,%1,%2,%3}, {%4,%5,%6,%7}, {%8,%9}, {%0,%1,%2,%3};\n"
        : "+f"(c[0]), "+f"(c[1]), "+f"(c[2]), "+f"(c[3])
        : "r"(a0), "r"(a1), "r"(a2), "r"(a3), "r"(b0), "r"(b1));
}

// split two fp32 into packed bf16 hi/lo words (elem0 in low half)
__device__ __forceinline__ void split2(float f0, float f1, uint32_t& hi, uint32_t& lo) {
    __nv_bfloat16 h0 = __float2bfloat16(f0), h1 = __float2bfloat16(f1);
    float r0 = f0 - __bfloat162float(h0);
    float r1 = f1 - __bfloat162float(h1);
    __nv_bfloat16 l0 = __float2bfloat16(r0), l1 = __float2bfloat16(r1);
    hi = ((uint32_t)__bfloat16_as_ushort(h1) << 16) | (uint32_t)__bfloat16_as_ushort(h0);
    lo = ((uint32_t)__bfloat16_as_ushort(l1) << 16) | (uint32_t)__bfloat16_as_ushort(l0);
}

__device__ __forceinline__ unsigned fmap(float f) {
    unsigned u = __float_as_uint(f);
    return (u & 0x80000000u) ? ~u : (u | 0x80000000u);
}

// ---------------------------------------------------------------------------
__global__ void detect_kernel(const int* __restrict__ qlabel_raw) {
    if (threadIdx.x == 0 && blockIdx.x == 0) {
        int is64 = 1;
        for (int i = 0; i < 4096; i++) {
            if (qlabel_raw[2 * i + 1] != 0) { is64 = 0; break; }
        }
        g_is64 = is64;
    }
}
__device__ __forceinline__ long long load_label(const void* p, int i) {
    if (g_is64) return ((const long long*)p)[i];
    return (long long)((const int*)p)[i];
}

// ---------------------------------------------------------------------------
// convA: [normq;kfeat] (1024x256 fp32) -> Ahi/Alo.
// ---------------------------------------------------------------------------
__global__ void __launch_bounds__(256) convA_kernel(const float* __restrict__ nq,
                                                    const float* __restrict__ kf) {
    size_t i = ((size_t)blockIdx.x * 256 + threadIdx.x) * 4;
    const size_t half = (size_t)512 * Dd;
    const float* src = (i < half) ? (nq + i) : (kf + (i - half));
    float4 v = *(const float4*)src;
    uint32_t h0, l0, h1, l1;
    split2(v.x, v.y, h0, l0);
    split2(v.z, v.w, h1, l1);
    *(uint2*)(g_Ahi + i) = make_uint2(h0, h1);
    *(uint2*)(g_Alo + i) = make_uint2(l0, l1);
}

// ---------------------------------------------------------------------------
// convQ: queue [256][65536] fp32 -> QThi/QTlo [65536][256] (transpose+split)
// ---------------------------------------------------------------------------
__global__ void __launch_bounds__(256) convQ_kernel(const float* __restrict__ Q) {
    __shared__ float s[32][65];
    const int n0 = blockIdx.x * 32, d0 = blockIdx.y * 64;
    const int t = threadIdx.x;
    const int nl = t & 31, dl = t >> 5;
    #pragma unroll
    for (int i = 0; i < 8; i++) {
        int d = i * 8 + dl;
        s[nl][d] = Q[(size_t)(d0 + d) * Kq + n0 + nl];
    }
    __syncthreads();
    const int n = t >> 3, dq = (t & 7) * 8;
    uint32_t hi[4], lo[4];
    #pragma unroll
    for (int j = 0; j < 4; j++)
        split2(s[n][dq + 2 * j], s[n][dq + 2 * j + 1], hi[j], lo[j]);
    size_t off = (size_t)(n0 + n) * Dd + d0 + dq;
    *(uint4*)(g_QThi + off) = make_uint4(hi[0], hi[1], hi[2], hi[3]);
    *(uint4*)(g_QTlo + off) = make_uint4(lo[0], lo[1], lo[2], lo[3]);
}

// ---------------------------------------------------------------------------
// convP: P [1000][65536] fp32 -> Phi/Plo [1024][65536] (rows >= 1000 zero)
// ---------------------------------------------------------------------------
__global__ void __launch_bounds__(256) convP_kernel(const float* __restrict__ P) {
    const int c = blockIdx.y;
    const size_t k = (size_t)blockIdx.x * 2048 + threadIdx.x * 8;
    size_t off = (size_t)c * Kq + k;
    uint32_t hi[4], lo[4];
    if (c < Cc) {
        float4 v0 = *(const float4*)(P + off);
        float4 v1 = *(const float4*)(P + off + 4);
        split2(v0.x, v0.y, hi[0], lo[0]);
        split2(v0.z, v0.w, hi[1], lo[1]);
        split2(v1.x, v1.y, hi[2], lo[2]);
        split2(v1.z, v1.w, hi[3], lo[3]);
    } else {
        hi[0] = hi[1] = hi[2] = hi[3] = 0u;
        lo[0] = lo[1] = lo[2] = lo[3] = 0u;
    }
    *(uint4*)(g_Phi + off) = make_uint4(hi[0], hi[1], hi[2], hi[3]);
    *(uint4*)(g_Plo + off) = make_uint4(lo[0], lo[1], lo[2], lo[3]);
}

// ---------------------------------------------------------------------------
// Shared GEMM machinery: CTA tile 128x128, kc=32, double-buffered cp.async.
// smem per stage (u32 words): Ah 2560 | Al 2560 | Bh 2560 | Bl 2560 = 10240
// total 2 stages = 20480 u32 = 80 KB.
// Warps: 2(M) x 4(N); warp tile 64x32; per-thread acc[4][4][4].
// ---------------------------------------------------------------------------
#define STG 10240

__device__ __forceinline__ void g_load_stage(
    uint32_t sbase, int buf,
    const __nv_bfloat16* Ah, const __nv_bfloat16* Al,
    const __nv_bfloat16* Bh, const __nv_bfloat16* Bl,
    size_t kstride, int kc, int tid)
{
    const int r = tid >> 1;
    const int c0 = (tid & 1) * 2;
    const uint32_t so = sbase + (uint32_t)buf * (STG * 4);
    #pragma unroll
    for (int i = 0; i < 2; i++) {
        int c = c0 + i;
        uint32_t off = (uint32_t)(r * PADW + c * 4) * 4;
        size_t goff = (size_t)r * kstride + kc + c * 8;
        cp16(so + off,                 Ah + goff);
        cp16(so + 2560 * 4 + off,      Al + goff);
        cp16(so + 5120 * 4 + off,      Bh + goff);
        cp16(so + 7680 * 4 + off,      Bl + goff);
    }
}

__device__ __forceinline__ void g_compute_stage(
    const uint32_t* sm, int buf, float acc[4][4][4],
    int wm, int wn, int g, int tig)
{
    const uint32_t* Ahp = sm + buf * STG;
    const uint32_t* Alp = Ahp + 2560;
    const uint32_t* Bhp = Ahp + 5120;
    const uint32_t* Blp = Ahp + 7680;
    #pragma unroll
    for (int ks = 0; ks < 2; ks++) {
        const int w = ks * 8 + tig;
        uint32_t ah[4][4], al[4][4];
        #pragma unroll
        for (int m = 0; m < 4; m++) {
            int r0 = wm * 64 + m * 16 + g, r1 = r0 + 8;
            ah[m][0] = Ahp[r0 * PADW + w];     ah[m][1] = Ahp[r1 * PADW + w];
            ah[m][2] = Ahp[r0 * PADW + w + 4]; ah[m][3] = Ahp[r1 * PADW + w + 4];
            al[m][0] = Alp[r0 * PADW + w];     al[m][1] = Alp[r1 * PADW + w];
            al[m][2] = Alp[r0 * PADW + w + 4]; al[m][3] = Alp[r1 * PADW + w + 4];
        }
        #pragma unroll
        for (int n = 0; n < 4; n++) {
            int nr = wn * 32 + n * 8 + g;
            uint32_t bh0 = Bhp[nr * PADW + w], bh1 = Bhp[nr * PADW + w + 4];
            uint32_t bl0 = Blp[nr * PADW + w], bl1 = Blp[nr * PADW + w + 4];
            #pragma unroll
            for (int m = 0; m < 4; m++) {
                mma_bf16(acc[m][n], ah[m][0], ah[m][1], ah[m][2], ah[m][3], bh0, bh1);
                mma_bf16(acc[m][n], ah[m][0], ah[m][1], ah[m][2], ah[m][3], bl0, bl1);
                mma_bf16(acc[m][n], al[m][0], al[m][1], al[m][2], al[m][3], bh0, bh1);
            }
        }
    }
}

// ---------------------------------------------------------------------------
// GEMM1: [A;..](1024x256) @ QT^T(per-row k-major) -> sim (mt<4) / E (mt>=4)
// grid (nt=512, mt=8), 256 threads.
// ---------------------------------------------------------------------------
__global__ void __launch_bounds__(256) gemm1_mma() {
    extern __shared__ __align__(16) uint32_t sm[];
    const int nt = blockIdx.x;   // 0..511
    const int mt = blockIdx.y;   // 0..7
    const int tid = threadIdx.x;
    const int lane = tid & 31, wid = tid >> 5;
    const int wm = wid >> 2, wn = wid & 3;
    const int g = lane >> 2, tig = lane & 3;
    const uint32_t sbase = smem_u32(sm);

    const __nv_bfloat16* Ah = g_Ahi + (size_t)mt * 128 * Dd;
    const __nv_bfloat16* Al = g_Alo + (size_t)mt * 128 * Dd;
    const __nv_bfloat16* Bh = g_QThi + (size_t)nt * 128 * Dd;
    const __nv_bfloat16* Bl = g_QTlo + (size_t)nt * 128 * Dd;

    float acc[4][4][4] = {};
    const int NS = Dd / 32;   // 8

    g_load_stage(sbase, 0, Ah, Al, Bh, Bl, Dd, 0, tid);
    CPCOMMIT();
    for (int s = 0; s < NS; s++) {
        if (s + 1 < NS) {
            g_load_stage(sbase, (s + 1) & 1, Ah, Al, Bh, Bl, Dd, (s + 1) * 32, tid);
            CPCOMMIT();
            asm volatile("cp.async.wait_group 1;\n" ::: "memory");
        } else {
            asm volatile("cp.async.wait_group 0;\n" ::: "memory");
        }
        __syncthreads();
        g_compute_stage(sm, s & 1, acc, wm, wn, g, tig);
        __syncthreads();
    }

    // epilogue
    const int rbase = mt * 128 + wm * 64;
    const int col = nt * 128 + wn * 32;
    if (mt < 4) {
        #pragma unroll
        for (int m = 0; m < 4; m++) {
            int r0 = rbase + m * 16 + g;
            #pragma unroll
            for (int n = 0; n < 4; n++) {
                int c = col + n * 8 + tig * 2;
                *(float2*)&g_sim[(size_t)r0 * Kq + c] = make_float2(acc[m][n][0], acc[m][n][1]);
                *(float2*)&g_sim[(size_t)(r0 + 8) * Kq + c] = make_float2(acc[m][n][2], acc[m][n][3]);
            }
        }
    } else {
        #pragma unroll
        for (int m = 0; m < 4; m++) {
            int b0 = rbase - 512 + m * 16 + g;
            float s0 = 0.f, s1 = 0.f;
            #pragma unroll
            for (int n = 0; n < 4; n++) {
                int c = col + n * 8 + tig * 2;
                float e0 = __expf(acc[m][n][0] * (1.0f / T_DCf));
                float e1 = __expf(acc[m][n][1] * (1.0f / T_DCf));
                float e2 = __expf(acc[m][n][2] * (1.0f / T_DCf));
                float e3 = __expf(acc[m][n][3] * (1.0f / T_DCf));
                uint32_t h, l;
                split2(e0, e1, h, l);
                *(uint32_t*)&g_Ehi[(size_t)b0 * Kq + c] = h;
                *(uint32_t*)&g_Elo[(size_t)b0 * Kq + c] = l;
                split2(e2, e3, h, l);
                *(uint32_t*)&g_Ehi[(size_t)(b0 + 8) * Kq + c] = h;
                *(uint32_t*)&g_Elo[(size_t)(b0 + 8) * Kq + c] = l;
                s0 += e0 + e1;
                s1 += e2 + e3;
            }
            s0 += __shfl_xor_sync(0xffffffffu, s0, 1);
            s0 += __shfl_xor_sync(0xffffffffu, s0, 2);
            s1 += __shfl_xor_sync(0xffffffffu, s1, 1);
            s1 += __shfl_xor_sync(0xffffffffu, s1, 2);
            if (tig == 0) {
                g_psum[(size_t)b0 * 2048 + nt * 4 + wn] = s0;
                g_psum[(size_t)(b0 + 8) * 2048 + nt * 4 + wn] = s1;
            }
        }
    }
}

// ---------------------------------------------------------------------------
// GEMM2 (split-K): part[sp] = E(512x65536) @ Pbf^T(1024x65536, k-major rows)
// grid (nt=8, mt=4, sp=8), 256 threads.
// ---------------------------------------------------------------------------
__global__ void __launch_bounds__(256) gemm2_mma() {
    extern __shared__ __align__(16) uint32_t sm[];
    const int nt = blockIdx.x;   // 0..7
    const int mt = blockIdx.y;   // 0..3
    const int sp = blockIdx.z;   // 0..7
    const int tid = threadIdx.x;
    const int lane = tid & 31, wid = tid >> 5;
    const int wm = wid >> 2, wn = wid & 3;
    const int g = lane >> 2, tig = lane & 3;
    const uint32_t sbase = smem_u32(sm);

    const size_t k0 = (size_t)sp * (Kq / SPLIT);
    const __nv_bfloat16* Ah = g_Ehi + (size_t)mt * 128 * Kq + k0;
    const __nv_bfloat16* Al = g_Elo + (size_t)mt * 128 * Kq + k0;
    const __nv_bfloat16* Bh = g_Phi + (size_t)nt * 128 * Kq + k0;
    const __nv_bfloat16* Bl = g_Plo + (size_t)nt * 128 * Kq + k0;

    float acc[4][4][4] = {};
    const int NS = (Kq / SPLIT) / 32;   // 256

    g_load_stage(sbase, 0, Ah, Al, Bh, Bl, Kq, 0, tid);
    CPCOMMIT();
    for (int s = 0; s < NS; s++) {
        if (s + 1 < NS) {
            g_load_stage(sbase, (s + 1) & 1, Ah, Al, Bh, Bl, Kq, (s + 1) * 32, tid);
            CPCOMMIT();
            asm volatile("cp.async.wait_group 1;\n" ::: "memory");
        } else {
            asm volatile("cp.async.wait_group 0;\n" ::: "memory");
        }
        __syncthreads();
        g_compute_stage(sm, s & 1, acc, wm, wn, g, tig);
        __syncthreads();
    }

    // epilogue: write split-K partials
    #pragma unroll
    for (int m = 0; m < 4; m++) {
        int b = mt * 128 + wm * 64 + m * 16 + g;
        #pragma unroll
        for (int n = 0; n < 4; n++) {
            int c = nt * 128 + wn * 32 + n * 8 + tig * 2;
            *(float2*)&g_part[((size_t)sp * 512 + b) * Cpad + c] =
                make_float2(acc[m][n][0], acc[m][n][1]);
            *(float2*)&g_part[((size_t)sp * 512 + b + 8) * Cpad + c] =
                make_float2(acc[m][n][2], acc[m][n][3]);
        }
    }
}

// ---------------------------------------------------------------------------
// invz: reduce 2048 per-tile partials -> 1/Z per row.
// ---------------------------------------------------------------------------
__global__ void __launch_bounds__(256) invz_kernel() {
    const int b = blockIdx.x;
    const int tid = threadIdx.x;
    float s = 0.f;
    for (int i = tid; i < 2048; i += 256) s += g_psum[(size_t)b * 2048 + i];
    __shared__ float red[256];
    red[tid] = s;
    __syncthreads();
    for (int o = 128; o > 0; o >>= 1) {
        if (tid < o) red[tid] += red[tid + o];
        __syncthreads();
    }
    if (tid == 0) g_invZ[b] = 1.0f / red[0];
}

// ---------------------------------------------------------------------------
// supcon: radix-select 200th largest per row + softmax-set sums.
// ---------------------------------------------------------------------------
#define MAXTIES 2048
__global__ void __launch_bounds__(256) supcon_kernel(
    const void* __restrict__ qlabel,
    const void* __restrict__ target,
    const int*  __restrict__ knnk)
{
    const int b = blockIdx.x;
    const float* row = g_sim + (size_t)b * Kq;
    const int tid = threadIdx.x;
    const int NT = 256;
    const int kneed = knnk[0];

    __shared__ unsigned hist[256];
    __shared__ unsigned s_prefix, s_desired;
    __shared__ int s_ties;
    __shared__ int tie_idx[MAXTIES];
    __shared__ float ra[256], rp[256];

    if (tid == 0) { s_prefix = 0; s_desired = (unsigned)kneed; }
    __syncthreads();

    for (int pass = 0; pass < 4; pass++) {
        const int shift = 24 - pass * 8;
        for (int i = tid; i < 256; i += NT) hist[i] = 0;
        __syncthreads();
        const unsigned pref = s_prefix;
        for (int k = tid; k < Kq; k += NT) {
            unsigned u = fmap(row[k]);
            bool ok = (pass == 0) || ((u >> (shift + 8)) == pref);
            if (ok) atomicAdd(&hist[(u >> shift) & 255u], 1u);
        }
        __syncthreads();
        if (tid == 0) {
            unsigned des = s_desired;
            for (int bin = 255; bin >= 0; bin--) {
                unsigned c = hist[bin];
                if (c >= des) {
                    s_prefix = (pref << 8) | (unsigned)bin;
                    s_desired = des;
                    break;
                }
                des -= c;
            }
        }
        __syncthreads();
    }

    const unsigned u200 = s_prefix;
    const unsigned des = s_desired;
    if (tid == 0) s_ties = 0;
    __syncthreads();

    float sa = 0.f, sp = 0.f;
    const long long tgt = load_label(target, b);
    for (int k = tid; k < Kq; k += NT) {
        float sv = row[k];
        unsigned u = fmap(sv);
        if (u > u200) {
            float e = __expf(sv * (1.0f / T_SUPf));
            sa += e;
            if (load_label(qlabel, k) == tgt) sp += e;
        } else if (u == u200) {
            int p = atomicAdd(&s_ties, 1);
            if (p < MAXTIES) tie_idx[p] = k;
        }
    }
    ra[tid] = sa; rp[tid] = sp;
    __syncthreads();
    for (int o = 128; o > 0; o >>= 1) {
        if (tid < o) { ra[tid] += ra[tid + o]; rp[tid] += rp[tid + o]; }
        __syncthreads();
    }

    if (tid == 0) {
        float SA = ra[0], SP = rp[0];
        int t = min(s_ties, MAXTIES);
        for (int i = 1; i < t; i++) {
            int v = tie_idx[i]; int j = i - 1;
            while (j >= 0 && tie_idx[j] > v) { tie_idx[j + 1] = tie_idx[j]; j--; }
            tie_idx[j + 1] = v;
        }
        int take = min((int)des, t);
        for (int i = 0; i < take; i++) {
            int k = tie_idx[i];
            float e = __expf(row[k] * (1.0f / T_SUPf));
            SA += e;
            if (load_label(qlabel, k) == tgt) SP += e;
        }
        float gt = SP / SA;
        g_row_supin[b] = (gt > EPSf) ? (-__logf(gt)) : 0.0f;
    }
}

// ---------------------------------------------------------------------------
// fc + dc per-row losses.
// ---------------------------------------------------------------------------
__global__ void __launch_bounds__(256) fcdc_kernel(
    const float* __restrict__ qlog,
    const void* __restrict__ target)
{
    const int b = blockIdx.x;
    const int tid = threadIdx.x;
    const float* q = qlog + (size_t)b * Cc;
    __shared__ float red[256];

    float mx = -3.4e38f;
    for (int c = tid; c < Cc; c += 256) mx = fmaxf(mx, q[c]);
    red[tid] = mx; __syncthreads();
    for (int o = 128; o > 0; o >>= 1) { if (tid < o) red[tid] = fmaxf(red[tid], red[tid + o]); __syncthreads(); }
    const float Mx = red[0]; __syncthreads();

    float mn = 3.4e38f;
    for (int c = tid; c < Cc; c += 256) mn = fminf(mn, q[c]);
    red[tid] = mn; __syncthreads();
    for (int o = 128; o > 0; o >>= 1) { if (tid < o) red[tid] = fminf(red[tid], red[tid + o]); __syncthreads(); }
    const float Mn = red[0]; __syncthreads();

    float se = 0.f;
    for (int c = tid; c < Cc; c += 256) se += __expf(q[c] - Mx);
    red[tid] = se; __syncthreads();
    for (int o = 128; o > 0; o >>= 1) { if (tid < o) red[tid] += red[tid + o]; __syncthreads(); }
    const float SE = red[0]; __syncthreads();

    const float logZ = __logf(SE);
    const bool qmask = (__expf(Mn - Mx) / SE) > EPSf;
    const float invZk = g_invZ[b];
    const long long t = load_label(target, b);

    float fcs = 0.f, kl = 0.f;
    for (int c = tid; c < Cc; c += 256) {
        float lq = q[c] - Mx - logZ;
        float oh = (c == (int)t) ? (1.0f - LSm) : (LSm / (float)(Cc - 1));
        fcs += oh * lq;
        float ps = 0.f;
        #pragma unroll
        for (int s = 0; s < SPLIT; s++)
            ps += g_part[((size_t)s * 512 + b) * Cpad + c];
        float dct = invZk * ps;
        if (dct > 0.f) kl += dct * (__logf(dct) - lq);
    }
    red[tid] = fcs; __syncthreads();
    for (int o = 128; o > 0; o >>= 1) { if (tid < o) red[tid] += red[tid + o]; __syncthreads(); }
    const float FCS = red[0]; __syncthreads();
    red[tid] = kl; __syncthreads();
    for (int o = 128; o > 0; o >>= 1) { if (tid < o) red[tid] += red[tid + o]; __syncthreads(); }
    if (tid == 0) {
        g_row_fc[b] = qmask ? FCS : 0.f;
        g_row_dc[b] = qmask ? red[0] : 0.f;
    }
}

// ---------------------------------------------------------------------------
__global__ void __launch_bounds__(512) finalize_kernel(float* __restrict__ out) {
    const int tid = threadIdx.x;
    __shared__ float r[512];

    r[tid] = g_row_supin[tid]; __syncthreads();
    for (int o = 256; o > 0; o >>= 1) { if (tid < o) r[tid] += r[tid + o]; __syncthreads(); }
    if (tid == 0) out[0] = r[0] / (float)Bsz;
    __syncthreads();

    r[tid] = g_row_fc[tid]; __syncthreads();
    for (int o = 256; o > 0; o >>= 1) { if (tid < o) r[tid] += r[tid + o]; __syncthreads(); }
    if (tid == 0) out[1] = -r[0] / (float)Bsz;
    __syncthreads();

    r[tid] = g_row_dc[tid]; __syncthreads();
    for (int o = 256; o > 0; o >>= 1) { if (tid < o) r[tid] += r[tid + o]; __syncthreads(); }
    if (tid == 0) out[2] = r[0] / (float)Bsz;
}

// ---------------------------------------------------------------------------
extern "C" void kernel_launch(void* const* d_in, const int* in_sizes, int n_in,
                              void* d_out, int out_size)
{
    const float* normq  = (const float*)d_in[0];
    const float* qlog   = (const float*)d_in[1];
    const float* kfeat  = (const float*)d_in[2];
    // d_in[3] = logits_k (unused)
    const float* queue  = (const float*)d_in[4];
    const float* qlp    = (const float*)d_in[5];
    const void*  qlabel = d_in[6];
    const void*  target = d_in[7];
    const int*   knnk   = (const int*)d_in[8];
    float* out = (float*)d_out;

    const int SMEM = 2 * STG * 4;  // 80 KB
    cudaFuncSetAttribute(gemm1_mma, cudaFuncAttributeMaxDynamicSharedMemorySize, SMEM);
    cudaFuncSetAttribute(gemm2_mma, cudaFuncAttributeMaxDynamicSharedMemorySize, SMEM);

    detect_kernel<<<1, 32>>>((const int*)qlabel);
    convA_kernel<<<256, 256>>>(normq, kfeat);
    convQ_kernel<<<dim3(2048, 4), 256>>>(queue);
    convP_kernel<<<dim3(32, 1024), 256>>>(qlp);
    gemm1_mma<<<dim3(512, 8), 256, SMEM>>>();
    supcon_kernel<<<512, 256>>>(qlabel, target, knnk);
    invz_kernel<<<512, 256>>>();
    gemm2_mma<<<dim3(8, 4, 8), 256, SMEM>>>();
    fcdc_kernel<<<512, 256>>>(qlog, target);
    finalize_kernel<<<1, 512>>>(out);
    (void)in_sizes; (void)n_in; (void)out_size;
}